// round 1
// baseline (speedup 1.0000x reference)
#include <cuda_runtime.h>
#include <cuda_bf16.h>

// Problem constants (fixed by the dataset)
#define NMAX 100000
#define EMAX 1280000
#define D 64

// Scratch (static __device__ — no allocation allowed)
__device__ float g_h[NMAX * D];     // transformed embeddings, 25.6 MB
__device__ float g_deg[NMAX];       // out-degree of source nodes

// ---------------------------------------------------------------------------
// Zero deg + output (output buffer is poisoned each run)
// ---------------------------------------------------------------------------
__global__ void zero_kernel(float* __restrict__ out, int N) {
    int i = blockIdx.x * blockDim.x + threadIdx.x;
    int total = N * D;
    if (i < total) out[i] = 0.0f;
    if (i < N) g_deg[i] = 0.0f;
}

// ---------------------------------------------------------------------------
// Degree histogram over source nodes
// ---------------------------------------------------------------------------
__global__ void deg_kernel(const int* __restrict__ n1, int E) {
    int e = blockIdx.x * blockDim.x + threadIdx.x;
    if (e < E) atomicAdd(&g_deg[n1[e]], 1.0f);
}

// ---------------------------------------------------------------------------
// h = X @ W^T + b   (X: N x 64, W: 64 x 64 row-major, h[i][j] = b[j] + sum_k X[i][k]*W[j][k])
// blockDim = (64, 8); each block computes 16 rows (2 rows per thread).
// ---------------------------------------------------------------------------
#define GEMM_ROWS 16
__global__ void gemm_kernel(const float* __restrict__ X,
                            const float* __restrict__ W,
                            const float* __restrict__ b,
                            int N) {
    __shared__ float Wt[D][D + 1];      // Wt[k][j] = W[j][k]  (transposed, padded)
    __shared__ float Xs[GEMM_ROWS][D];

    int tx = threadIdx.x;               // j: 0..63
    int ty = threadIdx.y;               // 0..7
    int tid = ty * 64 + tx;             // 0..511

    // Load W transposed
    for (int i = tid; i < D * D; i += 512) {
        int j = i / D, k = i % D;
        Wt[k][j] = W[i];
    }
    // Load 16 rows of X
    int row0 = blockIdx.x * GEMM_ROWS;
    for (int i = tid; i < GEMM_ROWS * D; i += 512) {
        int r = i / D, k = i % D;
        int row = row0 + r;
        Xs[r][k] = (row < N) ? X[row * D + k] : 0.0f;
    }
    __syncthreads();

    float bias = b[tx];
    #pragma unroll
    for (int rr = 0; rr < 2; rr++) {
        int r = ty + rr * 8;
        int row = row0 + r;
        if (row < N) {
            float acc = bias;
            #pragma unroll
            for (int k = 0; k < D; k++) acc += Xs[r][k] * Wt[k][tx];
            g_h[row * D + tx] = acc;
        }
    }
}

// ---------------------------------------------------------------------------
// Edge scatter: out[n1[e]] += w[e] * h[n2[e]]
// 16 lanes per edge, one float4 per lane, vectorized red.global.add.v4.f32
// ---------------------------------------------------------------------------
__device__ __forceinline__ void red_add_v4(float* addr, float4 v) {
    asm volatile("red.global.add.v4.f32 [%0], {%1, %2, %3, %4};"
                 :: "l"(addr), "f"(v.x), "f"(v.y), "f"(v.z), "f"(v.w)
                 : "memory");
}

__global__ void edge_kernel(const int* __restrict__ n1,
                            const int* __restrict__ n2,
                            const float* __restrict__ dist,
                            float* __restrict__ out,
                            int E) {
    int gid = blockIdx.x * blockDim.x + threadIdx.x;
    int e = gid >> 4;          // 16 lanes per edge
    int q = gid & 15;          // float4 index within the 64-float row
    if (e >= E) return;

    int a = n1[e];
    int c = n2[e];
    float dv = dist[e];
    float w = rsqrtf(g_deg[a] * g_deg[c]) * __expf(-dv * dv);

    const float4* hrow = reinterpret_cast<const float4*>(g_h + (size_t)c * D);
    float4 v = hrow[q];
    v.x *= w; v.y *= w; v.z *= w; v.w *= w;
    red_add_v4(out + (size_t)a * D + q * 4, v);
}

// ---------------------------------------------------------------------------
// Finalize: leaky_relu then L2-normalize each row. One warp per node.
// ---------------------------------------------------------------------------
__global__ void finalize_kernel(float* __restrict__ out, int N) {
    int warp = (blockIdx.x * blockDim.x + threadIdx.x) >> 5;
    int lane = threadIdx.x & 31;
    if (warp >= N) return;

    float2* p = reinterpret_cast<float2*>(out + (size_t)warp * D);
    float2 v = p[lane];
    v.x = (v.x >= 0.0f) ? v.x : 0.01f * v.x;
    v.y = (v.y >= 0.0f) ? v.y : 0.01f * v.y;
    float ss = v.x * v.x + v.y * v.y;
    #pragma unroll
    for (int o = 16; o > 0; o >>= 1) ss += __shfl_xor_sync(0xffffffffu, ss, o);
    float inv = 1.0f / fmaxf(sqrtf(ss), 1e-12f);
    v.x *= inv; v.y *= inv;
    p[lane] = v;
}

// ---------------------------------------------------------------------------
// Launch
// ---------------------------------------------------------------------------
extern "C" void kernel_launch(void* const* d_in, const int* in_sizes, int n_in,
                              void* d_out, int out_size) {
    const float* poi  = (const float*)d_in[0];
    const int*   eidx = (const int*)d_in[1];
    const float* dist = (const float*)d_in[2];
    const float* W    = (const float*)d_in[3];
    const float* b    = (const float*)d_in[4];
    float* out = (float*)d_out;

    int N = in_sizes[0] / D;
    int E = in_sizes[1] / 2;
    const int* n1 = eidx;
    const int* n2 = eidx + E;

    // 1. zero out + deg
    {
        int total = N * D;
        int blocks = (total + 255) / 256;
        zero_kernel<<<blocks, 256>>>(out, N);
    }
    // 2. degree histogram
    deg_kernel<<<(E + 255) / 256, 256>>>(n1, E);
    // 3. linear transform
    {
        dim3 bd(64, 8);
        int blocks = (N + GEMM_ROWS - 1) / GEMM_ROWS;
        gemm_kernel<<<blocks, bd>>>(poi, W, b, N);
    }
    // 4. edge scatter
    {
        long long threads = (long long)E * 16;
        int blocks = (int)((threads + 255) / 256);
        edge_kernel<<<blocks, 256>>>(n1, n2, dist, out, E);
    }
    // 5. leaky relu + normalize
    {
        long long threads = (long long)N * 32;
        int blocks = (int)((threads + 255) / 256);
        finalize_kernel<<<blocks, 256>>>(out, N);
    }
}

// round 2
// speedup vs baseline: 1.0699x; 1.0699x over previous
#include <cuda_runtime.h>
#include <cuda_bf16.h>

#define NMAX 100000
#define EMAX 1280000
#define D 64

__device__ float g_deg[NMAX];   // out-degree of source nodes
__device__ float g_sw[NMAX];    // per-node sum of edge weights

// ---------------------------------------------------------------------------
// Zero out + deg + sw  (out is poisoned each run)
// ---------------------------------------------------------------------------
__global__ void zero_kernel(float4* __restrict__ out4, int N) {
    int i = blockIdx.x * blockDim.x + threadIdx.x;
    int total4 = N * (D / 4);
    if (i < total4) out4[i] = make_float4(0.f, 0.f, 0.f, 0.f);
    if (i < N) { g_deg[i] = 0.0f; g_sw[i] = 0.0f; }
}

// ---------------------------------------------------------------------------
// Degree histogram over source nodes
// ---------------------------------------------------------------------------
__global__ void deg_kernel(const int* __restrict__ n1, int E) {
    int e = blockIdx.x * blockDim.x + threadIdx.x;
    if (e < E) atomicAdd(&g_deg[n1[e]], 1.0f);
}

// ---------------------------------------------------------------------------
// Edge scatter on RAW embeddings:  out[n1[e]] += w[e] * poi[n2[e]],
// g_sw[n1[e]] += w[e].  16 lanes per edge; weight computed once per edge in
// the leading lane of each 16-lane group and broadcast via shfl.
// ---------------------------------------------------------------------------
__device__ __forceinline__ void red_add_v4(float* addr, float4 v) {
    asm volatile("red.global.add.v4.f32 [%0], {%1, %2, %3, %4};"
                 :: "l"(addr), "f"(v.x), "f"(v.y), "f"(v.z), "f"(v.w)
                 : "memory");
}
__device__ __forceinline__ void red_add_f32(float* addr, float v) {
    asm volatile("red.global.add.f32 [%0], %1;" :: "l"(addr), "f"(v) : "memory");
}

__global__ void edge_kernel(const int* __restrict__ n1,
                            const int* __restrict__ n2,
                            const float* __restrict__ dist,
                            const float* __restrict__ X,
                            float* __restrict__ out,
                            int E) {
    int gid = blockIdx.x * blockDim.x + threadIdx.x;
    int e = gid >> 4;                 // edge id (16 lanes per edge)
    int lane = threadIdx.x & 31;
    int sub = lane & 15;              // float4 index within the 64-float row
    bool valid = (e < E);

    int a = 0, c = 0;
    float w = 0.0f;
    if (sub == 0 && valid) {
        a = n1[e];
        c = n2[e];
        float dv = dist[e];
        w = rsqrtf(g_deg[a] * g_deg[c]) * __expf(-dv * dv);
        red_add_f32(&g_sw[a], w);
    }
    // Broadcast from lane 0 / lane 16 of the warp (convergent shuffles)
    int src = lane & 16;
    a = __shfl_sync(0xffffffffu, a, src);
    c = __shfl_sync(0xffffffffu, c, src);
    w = __shfl_sync(0xffffffffu, w, src);
    if (!valid) return;

    const float4* xr = reinterpret_cast<const float4*>(X + (size_t)c * D);
    float4 v = xr[sub];
    v.x *= w; v.y *= w; v.z *= w; v.w *= w;
    red_add_v4(out + (size_t)a * D + sub * 4, v);
}

// ---------------------------------------------------------------------------
// Post: y = agg @ W^T + sw*b, leaky_relu, L2 normalize. In-place on out.
// Block = (64,8) = 512 threads, 32 rows per block (4 rows per thread-row).
// ---------------------------------------------------------------------------
#define POST_ROWS 32
__global__ void post_kernel(const float* __restrict__ W,
                            const float* __restrict__ b,
                            float* __restrict__ out, int N) {
    __shared__ float Wt[D][D + 1];         // Wt[k][j] = W[j*D+k]
    __shared__ float Xs[POST_ROWS][D];     // aggregated inputs
    __shared__ float Ys[POST_ROWS][D];     // transformed outputs
    __shared__ float sws[POST_ROWS];

    int tx = threadIdx.x;                  // output col j
    int ty = threadIdx.y;
    int tid = ty * 64 + tx;
    int row0 = blockIdx.x * POST_ROWS;

    for (int i = tid; i < D * D; i += 512) {
        int j = i / D, k = i % D;
        Wt[k][j] = W[i];
    }
    for (int i = tid; i < POST_ROWS * D; i += 512) {
        int r = i / D, k = i % D;
        int row = row0 + r;
        Xs[r][k] = (row < N) ? out[(size_t)row * D + k] : 0.0f;
    }
    if (tid < POST_ROWS) {
        int row = row0 + tid;
        sws[tid] = (row < N) ? g_sw[row] : 0.0f;
    }
    __syncthreads();

    float bias = b[tx];
    #pragma unroll
    for (int rr = 0; rr < POST_ROWS / 8; rr++) {
        int r = ty + rr * 8;
        float acc = sws[r] * bias;
        #pragma unroll
        for (int k = 0; k < D; k++) acc += Xs[r][k] * Wt[k][tx];
        Ys[r][tx] = acc;
    }
    __syncthreads();

    // 16 warps, 32 rows: each warp finalizes 2 rows
    int wid = tid >> 5;
    int l = tid & 31;
    #pragma unroll
    for (int rr = 0; rr < 2; rr++) {
        int r = wid + rr * 16;
        int row = row0 + r;
        if (row < N) {
            float vx = Ys[r][l * 2], vy = Ys[r][l * 2 + 1];
            vx = (vx >= 0.0f) ? vx : 0.01f * vx;
            vy = (vy >= 0.0f) ? vy : 0.01f * vy;
            float ss = vx * vx + vy * vy;
            #pragma unroll
            for (int o = 16; o > 0; o >>= 1) ss += __shfl_xor_sync(0xffffffffu, ss, o);
            float inv = 1.0f / fmaxf(sqrtf(ss), 1e-12f);
            float2 v = make_float2(vx * inv, vy * inv);
            reinterpret_cast<float2*>(out + (size_t)row * D)[l] = v;
        }
    }
}

// ---------------------------------------------------------------------------
// Launch
// ---------------------------------------------------------------------------
extern "C" void kernel_launch(void* const* d_in, const int* in_sizes, int n_in,
                              void* d_out, int out_size) {
    const float* poi  = (const float*)d_in[0];
    const int*   eidx = (const int*)d_in[1];
    const float* dist = (const float*)d_in[2];
    const float* W    = (const float*)d_in[3];
    const float* b    = (const float*)d_in[4];
    float* out = (float*)d_out;

    int N = in_sizes[0] / D;
    int E = in_sizes[1] / 2;
    const int* n1 = eidx;
    const int* n2 = eidx + E;

    {
        int total4 = N * (D / 4);
        zero_kernel<<<(total4 + 255) / 256, 256>>>((float4*)out, N);
    }
    deg_kernel<<<(E + 255) / 256, 256>>>(n1, E);
    {
        long long threads = (long long)E * 16;
        int blocks = (int)((threads + 255) / 256);
        edge_kernel<<<blocks, 256>>>(n1, n2, dist, poi, out, E);
    }
    {
        int blocks = (N + POST_ROWS - 1) / POST_ROWS;
        post_kernel<<<blocks, dim3(64, 8)>>>(W, b, out, N);
    }
}

// round 3
// speedup vs baseline: 1.2379x; 1.1570x over previous
#include <cuda_runtime.h>
#include <cuda_bf16.h>

#define NMAX 100000
#define EMAX 1280000
#define D 64

__device__ float g_deg[NMAX];   // out-degree of source nodes
__device__ float g_sw[NMAX];    // per-node sum of edge weights

// ---------------------------------------------------------------------------
// packed f32x2 helpers
// ---------------------------------------------------------------------------
typedef unsigned long long u64;
__device__ __forceinline__ u64 ffma2(u64 a, u64 b, u64 c) {
    u64 d;
    asm("fma.rn.f32x2 %0, %1, %2, %3;" : "=l"(d) : "l"(a), "l"(b), "l"(c));
    return d;
}
__device__ __forceinline__ u64 pack2(float lo, float hi) {
    u64 d;
    asm("mov.b64 %0, {%1, %2};" : "=l"(d) : "f"(lo), "f"(hi));
    return d;
}
__device__ __forceinline__ float lo32(u64 v) { return __uint_as_float((unsigned)v); }
__device__ __forceinline__ float hi32(u64 v) { return __uint_as_float((unsigned)(v >> 32)); }

// ---------------------------------------------------------------------------
// Zero out + deg + sw  (out is poisoned each run)
// ---------------------------------------------------------------------------
__global__ void zero_kernel(float4* __restrict__ out4, int N) {
    int i = blockIdx.x * blockDim.x + threadIdx.x;
    int total4 = N * (D / 4);
    if (i < total4) out4[i] = make_float4(0.f, 0.f, 0.f, 0.f);
    if (i < N) { g_deg[i] = 0.0f; g_sw[i] = 0.0f; }
}

// ---------------------------------------------------------------------------
// Degree histogram over source nodes
// ---------------------------------------------------------------------------
__global__ void deg_kernel(const int* __restrict__ n1, int E) {
    int e = blockIdx.x * blockDim.x + threadIdx.x;
    if (e < E) atomicAdd(&g_deg[n1[e]], 1.0f);
}

// ---------------------------------------------------------------------------
// Edge scatter on RAW embeddings:  out[n1[e]] += w[e] * poi[n2[e]],
// g_sw[n1[e]] += w[e].  16 lanes per edge, weight computed once + shfl bcast.
// ---------------------------------------------------------------------------
__device__ __forceinline__ void red_add_v4(float* addr, float4 v) {
    asm volatile("red.global.add.v4.f32 [%0], {%1, %2, %3, %4};"
                 :: "l"(addr), "f"(v.x), "f"(v.y), "f"(v.z), "f"(v.w)
                 : "memory");
}
__device__ __forceinline__ void red_add_f32(float* addr, float v) {
    asm volatile("red.global.add.f32 [%0], %1;" :: "l"(addr), "f"(v) : "memory");
}

__global__ void edge_kernel(const int* __restrict__ n1,
                            const int* __restrict__ n2,
                            const float* __restrict__ dist,
                            const float* __restrict__ X,
                            float* __restrict__ out,
                            int E) {
    int gid = blockIdx.x * blockDim.x + threadIdx.x;
    int e = gid >> 4;
    int lane = threadIdx.x & 31;
    int sub = lane & 15;
    bool valid = (e < E);

    int a = 0, c = 0;
    float w = 0.0f;
    if (sub == 0 && valid) {
        a = n1[e];
        c = n2[e];
        float dv = dist[e];
        w = rsqrtf(g_deg[a] * g_deg[c]) * __expf(-dv * dv);
        red_add_f32(&g_sw[a], w);
    }
    int src = lane & 16;
    a = __shfl_sync(0xffffffffu, a, src);
    c = __shfl_sync(0xffffffffu, c, src);
    w = __shfl_sync(0xffffffffu, w, src);
    if (!valid) return;

    const float4* xr = reinterpret_cast<const float4*>(X + (size_t)c * D);
    float4 v = xr[sub];
    v.x *= w; v.y *= w; v.z *= w; v.w *= w;
    red_add_v4(out + (size_t)a * D + sub * 4, v);
}

// ---------------------------------------------------------------------------
// Post: y = agg @ W^T + sw*b, leaky_relu, L2 normalize. In-place on out.
// 256 threads (8 warps), 64 rows/block. Warp w: rows w*8..w*8+7.
// Lane l: cols l and l+32. Accumulators packed f32x2 across ROW pairs.
// ---------------------------------------------------------------------------
#define PB_ROWS 64
#define XPAD 68
__global__ __launch_bounds__(256) void post_kernel(const float* __restrict__ W,
                                                   const float* __restrict__ b,
                                                   float* __restrict__ out, int N) {
    __shared__ u64   Wsp[D][D];        // Wsp[k][j] = splat(W[j][k]), 32 KB
    __shared__ float Xst[D][XPAD];     // Xst[k][r] = agg[row0+r][k], transposed
    __shared__ float sws[PB_ROWS];

    int tid = threadIdx.x;
    int wid = tid >> 5;
    int l = tid & 31;
    int row0 = blockIdx.x * PB_ROWS;

    // Load W transposed+splatted: consecutive tid -> consecutive j (STS.64 conflict-free).
    // Global reads stride-256B but W is 16KB and L1-resident across the block wave.
    for (int i = tid; i < D * D; i += 256) {
        int k = i >> 6, j = i & 63;
        float w = W[j * D + k];
        Wsp[k][j] = pack2(w, w);
    }
    // Load agg rows transposed (coalesced global reads)
    for (int i = tid; i < PB_ROWS * D; i += 256) {
        int r = i >> 6, k = i & 63;
        int row = row0 + r;
        Xst[k][r] = (row < N) ? out[(size_t)row * D + k] : 0.0f;
    }
    if (tid < PB_ROWS) {
        int row = row0 + tid;
        sws[tid] = (row < N) ? g_sw[row] : 0.0f;
    }
    __syncthreads();

    int r0 = wid * 8;
    float bl = b[l], bh = b[l + 32];
    u64 accL[4], accH[4];
    #pragma unroll
    for (int p = 0; p < 4; p++) {
        float s0 = sws[r0 + 2 * p], s1 = sws[r0 + 2 * p + 1];
        accL[p] = pack2(s0 * bl, s1 * bl);
        accH[p] = pack2(s0 * bh, s1 * bh);
    }

    #pragma unroll 8
    for (int k = 0; k < D; k++) {
        ulonglong2 xa = *reinterpret_cast<const ulonglong2*>(&Xst[k][r0]);      // rows r0..r0+3
        ulonglong2 xb = *reinterpret_cast<const ulonglong2*>(&Xst[k][r0 + 4]);  // rows r0+4..r0+7
        u64 wl = Wsp[k][l];
        u64 wh = Wsp[k][l + 32];
        accL[0] = ffma2(xa.x, wl, accL[0]);  accH[0] = ffma2(xa.x, wh, accH[0]);
        accL[1] = ffma2(xa.y, wl, accL[1]);  accH[1] = ffma2(xa.y, wh, accH[1]);
        accL[2] = ffma2(xb.x, wl, accL[2]);  accH[2] = ffma2(xb.x, wh, accH[2]);
        accL[3] = ffma2(xb.y, wl, accL[3]);  accH[3] = ffma2(xb.y, wh, accH[3]);
    }

    // Epilogue: leaky relu, row L2 norm (butterfly over lanes), write.
    float vL[8], vH[8], ss[8];
    #pragma unroll
    for (int p = 0; p < 4; p++) {
        vL[2 * p]     = lo32(accL[p]);  vL[2 * p + 1] = hi32(accL[p]);
        vH[2 * p]     = lo32(accH[p]);  vH[2 * p + 1] = hi32(accH[p]);
    }
    #pragma unroll
    for (int r = 0; r < 8; r++) {
        vL[r] = (vL[r] >= 0.0f) ? vL[r] : 0.01f * vL[r];
        vH[r] = (vH[r] >= 0.0f) ? vH[r] : 0.01f * vH[r];
        ss[r] = vL[r] * vL[r] + vH[r] * vH[r];
    }
    #pragma unroll
    for (int o = 16; o > 0; o >>= 1) {
        #pragma unroll
        for (int r = 0; r < 8; r++) ss[r] += __shfl_xor_sync(0xffffffffu, ss[r], o);
    }
    #pragma unroll
    for (int r = 0; r < 8; r++) {
        int row = row0 + r0 + r;
        if (row < N) {
            float inv = 1.0f / fmaxf(sqrtf(ss[r]), 1e-12f);
            out[(size_t)row * D + l]      = vL[r] * inv;
            out[(size_t)row * D + l + 32] = vH[r] * inv;
        }
    }
}

// ---------------------------------------------------------------------------
// Launch
// ---------------------------------------------------------------------------
extern "C" void kernel_launch(void* const* d_in, const int* in_sizes, int n_in,
                              void* d_out, int out_size) {
    const float* poi  = (const float*)d_in[0];
    const int*   eidx = (const int*)d_in[1];
    const float* dist = (const float*)d_in[2];
    const float* W    = (const float*)d_in[3];
    const float* b    = (const float*)d_in[4];
    float* out = (float*)d_out;

    int N = in_sizes[0] / D;
    int E = in_sizes[1] / 2;
    const int* n1 = eidx;
    const int* n2 = eidx + E;

    {
        int total4 = N * (D / 4);
        zero_kernel<<<(total4 + 255) / 256, 256>>>((float4*)out, N);
    }
    deg_kernel<<<(E + 255) / 256, 256>>>(n1, E);
    {
        long long threads = (long long)E * 16;
        int blocks = (int)((threads + 255) / 256);
        edge_kernel<<<blocks, 256>>>(n1, n2, dist, poi, out, E);
    }
    {
        int blocks = (N + PB_ROWS - 1) / PB_ROWS;
        post_kernel<<<blocks, 256>>>(W, b, out, N);
    }
}

// round 4
// speedup vs baseline: 1.5385x; 1.2429x over previous
#include <cuda_runtime.h>
#include <cuda_bf16.h>

#define NMAX 100000
#define EMAX 1280000
#define D 64

__device__ float g_deg[NMAX];   // out-degree of source nodes
__device__ float g_sw[NMAX];    // per-node sum of edge weights

typedef unsigned long long u64;
__device__ __forceinline__ u64 ffma2(u64 a, u64 b, u64 c) {
    u64 d;
    asm("fma.rn.f32x2 %0, %1, %2, %3;" : "=l"(d) : "l"(a), "l"(b), "l"(c));
    return d;
}
__device__ __forceinline__ u64 pack2(float lo, float hi) {
    u64 d;
    asm("mov.b64 %0, {%1, %2};" : "=l"(d) : "f"(lo), "f"(hi));
    return d;
}
__device__ __forceinline__ float lo32(u64 v) { return __uint_as_float((unsigned)v); }
__device__ __forceinline__ float hi32(u64 v) { return __uint_as_float((unsigned)(v >> 32)); }

// ---------------------------------------------------------------------------
// Zero out + deg + sw  (out is poisoned each run)
// ---------------------------------------------------------------------------
__global__ void zero_kernel(float4* __restrict__ out4, int N) {
    int i = blockIdx.x * blockDim.x + threadIdx.x;
    int total4 = N * (D / 4);
    if (i < total4) out4[i] = make_float4(0.f, 0.f, 0.f, 0.f);
    if (i < N) { g_deg[i] = 0.0f; g_sw[i] = 0.0f; }
}

// ---------------------------------------------------------------------------
// Degree histogram over source nodes
// ---------------------------------------------------------------------------
__global__ void deg_kernel(const int* __restrict__ n1, int E) {
    int e = blockIdx.x * blockDim.x + threadIdx.x;
    if (e < E) atomicAdd(&g_deg[n1[e]], 1.0f);
}

// ---------------------------------------------------------------------------
// Edge scatter on RAW embeddings:  out[n1[e]] += w[e] * poi[n2[e]],
// g_sw[n1[e]] += w[e].  16 lanes per edge, weight computed once + shfl bcast.
// ---------------------------------------------------------------------------
__device__ __forceinline__ void red_add_v4(float* addr, float4 v) {
    asm volatile("red.global.add.v4.f32 [%0], {%1, %2, %3, %4};"
                 :: "l"(addr), "f"(v.x), "f"(v.y), "f"(v.z), "f"(v.w)
                 : "memory");
}
__device__ __forceinline__ void red_add_f32(float* addr, float v) {
    asm volatile("red.global.add.f32 [%0], %1;" :: "l"(addr), "f"(v) : "memory");
}

__global__ void edge_kernel(const int* __restrict__ n1,
                            const int* __restrict__ n2,
                            const float* __restrict__ dist,
                            const float* __restrict__ X,
                            float* __restrict__ out,
                            int E) {
    int gid = blockIdx.x * blockDim.x + threadIdx.x;
    int e = gid >> 4;
    int lane = threadIdx.x & 31;
    int sub = lane & 15;
    bool valid = (e < E);

    int a = 0, c = 0;
    float w = 0.0f;
    if (sub == 0 && valid) {
        a = n1[e];
        c = n2[e];
        float dv = dist[e];
        w = rsqrtf(g_deg[a] * g_deg[c]) * __expf(-dv * dv);
        red_add_f32(&g_sw[a], w);
    }
    int src = lane & 16;
    a = __shfl_sync(0xffffffffu, a, src);
    c = __shfl_sync(0xffffffffu, c, src);
    w = __shfl_sync(0xffffffffu, w, src);
    if (!valid) return;

    const float4* xr = reinterpret_cast<const float4*>(X + (size_t)c * D);
    float4 v = xr[sub];
    v.x *= w; v.y *= w; v.z *= w; v.w *= w;
    red_add_v4(out + (size_t)a * D + sub * 4, v);
}

// ---------------------------------------------------------------------------
// Post: y = agg @ W^T + sw*b, leaky_relu, L2 normalize. In-place on out.
// 256 threads, 32 rows/block. Warp w: rows w*4..w*4+3; lane l: cols l, l+32.
// f32x2 accumulators packed over EVEN/ODD k (final value = lo+hi), so W is
// used in natural row-major u64 pairs (no splat, no transpose): 17KB smem.
// ---------------------------------------------------------------------------
#define PB_ROWS 32
#define WPITCH 33   // u64 pitch for Ws2 rows (conflict-free LDS.64)
#define XPITCH 34   // u64 pitch for Xst2 rows (16B-aligned LDS.128)
__global__ __launch_bounds__(256) void post_kernel(const float* __restrict__ W,
                                                   const float* __restrict__ b,
                                                   float* __restrict__ out, int N) {
    __shared__ u64 Ws2[D * WPITCH];          // Ws2[j*WPITCH+kp] = (W[j][2kp],W[j][2kp+1])
    __shared__ u64 Xst2[(D / 2) * XPITCH];   // Xst2[kp*XPITCH+r] = (agg[r][2kp],agg[r][2kp+1])
    __shared__ float sws[PB_ROWS];

    int tid = threadIdx.x;
    int wid = tid >> 5;
    int l = tid & 31;
    int row0 = blockIdx.x * PB_ROWS;

    // Load W as u64 pairs, row-major, padded pitch.
    const u64* W2 = reinterpret_cast<const u64*>(W);
    #pragma unroll
    for (int i = tid; i < D * (D / 2); i += 256) {
        int j = i >> 5, kp = i & 31;
        Ws2[j * WPITCH + kp] = W2[i];
    }
    // Load agg rows as u64 pairs, transposed into Xst2[kp][r].
    const u64* O2 = reinterpret_cast<const u64*>(out);
    #pragma unroll
    for (int i = tid; i < PB_ROWS * (D / 2); i += 256) {
        int r = i >> 5, kp = i & 31;
        int row = row0 + r;
        Xst2[kp * XPITCH + r] = (row < N) ? O2[(size_t)row * (D / 2) + kp] : 0ull;
    }
    if (tid < PB_ROWS) {
        int row = row0 + tid;
        sws[tid] = (row < N) ? g_sw[row] : 0.0f;
    }
    __syncthreads();

    int r0 = wid * 4;
    float bl = b[l], bh = b[l + 32];
    u64 accL[4], accH[4];
    #pragma unroll
    for (int r = 0; r < 4; r++) {
        float s = sws[r0 + r];
        accL[r] = pack2(s * bl, 0.0f);
        accH[r] = pack2(s * bh, 0.0f);
    }

    const u64* wrowL = &Ws2[l * WPITCH];
    const u64* wrowH = &Ws2[(l + 32) * WPITCH];
    #pragma unroll 4
    for (int kp = 0; kp < D / 2; kp++) {
        // 4 row-values for this k-pair: two 16B broadcast loads
        ulonglong2 x01 = *reinterpret_cast<const ulonglong2*>(&Xst2[kp * XPITCH + r0]);
        ulonglong2 x23 = *reinterpret_cast<const ulonglong2*>(&Xst2[kp * XPITCH + r0 + 2]);
        u64 wl = wrowL[kp];
        u64 wh = wrowH[kp];
        accL[0] = ffma2(x01.x, wl, accL[0]);  accH[0] = ffma2(x01.x, wh, accH[0]);
        accL[1] = ffma2(x01.y, wl, accL[1]);  accH[1] = ffma2(x01.y, wh, accH[1]);
        accL[2] = ffma2(x23.x, wl, accL[2]);  accH[2] = ffma2(x23.x, wh, accH[2]);
        accL[3] = ffma2(x23.y, wl, accL[3]);  accH[3] = ffma2(x23.y, wh, accH[3]);
    }

    // Epilogue: combine k-parities, leaky relu, row L2 norm, write.
    #pragma unroll
    for (int r = 0; r < 4; r++) {
        float vL = lo32(accL[r]) + hi32(accL[r]);
        float vH = lo32(accH[r]) + hi32(accH[r]);
        vL = (vL >= 0.0f) ? vL : 0.01f * vL;
        vH = (vH >= 0.0f) ? vH : 0.01f * vH;
        float ss = vL * vL + vH * vH;
        #pragma unroll
        for (int o = 16; o > 0; o >>= 1) ss += __shfl_xor_sync(0xffffffffu, ss, o);
        int row = row0 + r0 + r;
        if (row < N) {
            float inv = 1.0f / fmaxf(sqrtf(ss), 1e-12f);
            out[(size_t)row * D + l]      = vL * inv;
            out[(size_t)row * D + l + 32] = vH * inv;
        }
    }
}

// ---------------------------------------------------------------------------
// Launch
// ---------------------------------------------------------------------------
extern "C" void kernel_launch(void* const* d_in, const int* in_sizes, int n_in,
                              void* d_out, int out_size) {
    const float* poi  = (const float*)d_in[0];
    const int*   eidx = (const int*)d_in[1];
    const float* dist = (const float*)d_in[2];
    const float* W    = (const float*)d_in[3];
    const float* b    = (const float*)d_in[4];
    float* out = (float*)d_out;

    int N = in_sizes[0] / D;
    int E = in_sizes[1] / 2;
    const int* n1 = eidx;
    const int* n2 = eidx + E;

    {
        int total4 = N * (D / 4);
        zero_kernel<<<(total4 + 255) / 256, 256>>>((float4*)out, N);
    }
    deg_kernel<<<(E + 255) / 256, 256>>>(n1, E);
    {
        long long threads = (long long)E * 16;
        int blocks = (int)((threads + 255) / 256);
        edge_kernel<<<blocks, 256>>>(n1, n2, dist, poi, out, E);
    }
    {
        int blocks = (N + PB_ROWS - 1) / PB_ROWS;
        post_kernel<<<blocks, 256>>>(W, b, out, N);
    }
}

// round 5
// speedup vs baseline: 1.9134x; 1.2437x over previous
#include <cuda_runtime.h>
#include <cuda_bf16.h>

#define D 64
#define NMAX 100000
#define EMAX 1280000
#define SCAN_BS 1024

__device__ int   g_degi[NMAX];     // out-degree (int)
__device__ int   g_rowptr[NMAX];   // CSR row start
__device__ int   g_cur[NMAX];      // scatter cursors
__device__ int   g_bsums[256];     // scan block sums
__device__ float g_sw[NMAX];       // per-node sum of edge weights
__device__ int2  g_epack[EMAX];    // {dst node, weight bits} in CSR order

typedef unsigned long long u64;
__device__ __forceinline__ u64 ffma2(u64 a, u64 b, u64 c) {
    u64 d;
    asm("fma.rn.f32x2 %0, %1, %2, %3;" : "=l"(d) : "l"(a), "l"(b), "l"(c));
    return d;
}
__device__ __forceinline__ u64 pack2(float lo, float hi) {
    u64 d;
    asm("mov.b64 %0, {%1, %2};" : "=l"(d) : "f"(lo), "f"(hi));
    return d;
}
__device__ __forceinline__ float lo32(u64 v) { return __uint_as_float((unsigned)v); }
__device__ __forceinline__ float hi32(u64 v) { return __uint_as_float((unsigned)(v >> 32)); }

// ---------------------------------------------------------------------------
// 1. zero degree counters
// ---------------------------------------------------------------------------
__global__ void zero_deg_kernel(int N) {
    int i = blockIdx.x * blockDim.x + threadIdx.x;
    if (i < N) g_degi[i] = 0;
}

// ---------------------------------------------------------------------------
// 2. degree histogram over source nodes
// ---------------------------------------------------------------------------
__global__ void deg_kernel(const int* __restrict__ n1, int E) {
    int e = blockIdx.x * blockDim.x + threadIdx.x;
    if (e < E) atomicAdd(&g_degi[n1[e]], 1);
}

// ---------------------------------------------------------------------------
// 3-5. exclusive prefix scan of g_degi -> g_rowptr (3 tiny kernels)
// ---------------------------------------------------------------------------
__global__ void scan1_kernel(int N) {
    __shared__ int s[SCAN_BS];
    int tid = threadIdx.x;
    int i = blockIdx.x * SCAN_BS + tid;
    int v = (i < N) ? g_degi[i] : 0;
    s[tid] = v;
    __syncthreads();
    #pragma unroll
    for (int off = 1; off < SCAN_BS; off <<= 1) {
        int t = (tid >= off) ? s[tid - off] : 0;
        __syncthreads();
        s[tid] += t;
        __syncthreads();
    }
    if (i < N) g_rowptr[i] = s[tid] - v;   // exclusive within block
    if (tid == SCAN_BS - 1) g_bsums[blockIdx.x] = s[tid];
}

__global__ void scan2_kernel(int nb) {
    if (threadIdx.x == 0 && blockIdx.x == 0) {
        int run = 0;
        for (int b = 0; b < nb; b++) {
            int t = g_bsums[b];
            g_bsums[b] = run;
            run += t;
        }
    }
}

__global__ void scan3_kernel(int N) {
    int i = blockIdx.x * SCAN_BS + threadIdx.x;
    if (i < N) {
        int r = g_rowptr[i] + g_bsums[blockIdx.x];
        g_rowptr[i] = r;
        g_cur[i] = r;
    }
}

// ---------------------------------------------------------------------------
// 6. scatter edges into CSR order with precomputed weights
// ---------------------------------------------------------------------------
__global__ void scatter_kernel(const int* __restrict__ n1,
                               const int* __restrict__ n2,
                               const float* __restrict__ dist,
                               int E) {
    int e = blockIdx.x * blockDim.x + threadIdx.x;
    if (e >= E) return;
    int a = n1[e];
    int c = n2[e];
    float dv = dist[e];
    float w = rsqrtf(__int2float_rn(g_degi[a]) * __int2float_rn(g_degi[c])) * __expf(-dv * dv);
    int pos = atomicAdd(&g_cur[a], 1);
    g_epack[pos] = make_int2(c, __float_as_int(w));
}

// ---------------------------------------------------------------------------
// 7. per-node gather-accumulate: 16 lanes per node, register accumulation,
//    single write of agg row + sum of weights. No output atomics.
// ---------------------------------------------------------------------------
__global__ __launch_bounds__(256) void gather_kernel(const float* __restrict__ X,
                                                     float* __restrict__ out,
                                                     int N) {
    int gid = blockIdx.x * blockDim.x + threadIdx.x;
    int v = gid >> 4;            // node id
    int sub = gid & 15;          // float4 chunk within the 64-float row
    if (v >= N) return;

    int start = g_rowptr[v];
    int cnt = g_degi[v];
    const float4* X4 = reinterpret_cast<const float4*>(X);

    float4 acc = make_float4(0.f, 0.f, 0.f, 0.f);
    float swl = 0.0f;
    for (int j = 0; j < cnt; j++) {
        int2 p = g_epack[start + j];             // broadcast within the 16-lane group
        float w = __int_as_float(p.y);
        swl += w;
        float4 x = X4[(size_t)p.x * 16 + sub];
        acc.x = fmaf(w, x.x, acc.x);
        acc.y = fmaf(w, x.y, acc.y);
        acc.z = fmaf(w, x.z, acc.z);
        acc.w = fmaf(w, x.w, acc.w);
    }
    reinterpret_cast<float4*>(out)[(size_t)v * 16 + sub] = acc;
    if (sub == 0) g_sw[v] = swl;
}

// ---------------------------------------------------------------------------
// 8. Post: y = agg @ W^T + sw*b, leaky_relu, L2 normalize. In-place on out.
//    (unchanged from R4)
// ---------------------------------------------------------------------------
#define PB_ROWS 32
#define WPITCH 33
#define XPITCH 34
__global__ __launch_bounds__(256) void post_kernel(const float* __restrict__ W,
                                                   const float* __restrict__ b,
                                                   float* __restrict__ out, int N) {
    __shared__ u64 Ws2[D * WPITCH];
    __shared__ u64 Xst2[(D / 2) * XPITCH];
    __shared__ float sws[PB_ROWS];

    int tid = threadIdx.x;
    int wid = tid >> 5;
    int l = tid & 31;
    int row0 = blockIdx.x * PB_ROWS;

    const u64* W2 = reinterpret_cast<const u64*>(W);
    #pragma unroll
    for (int i = tid; i < D * (D / 2); i += 256) {
        int j = i >> 5, kp = i & 31;
        Ws2[j * WPITCH + kp] = W2[i];
    }
    const u64* O2 = reinterpret_cast<const u64*>(out);
    #pragma unroll
    for (int i = tid; i < PB_ROWS * (D / 2); i += 256) {
        int r = i >> 5, kp = i & 31;
        int row = row0 + r;
        Xst2[kp * XPITCH + r] = (row < N) ? O2[(size_t)row * (D / 2) + kp] : 0ull;
    }
    if (tid < PB_ROWS) {
        int row = row0 + tid;
        sws[tid] = (row < N) ? g_sw[row] : 0.0f;
    }
    __syncthreads();

    int r0 = wid * 4;
    float bl = b[l], bh = b[l + 32];
    u64 accL[4], accH[4];
    #pragma unroll
    for (int r = 0; r < 4; r++) {
        float s = sws[r0 + r];
        accL[r] = pack2(s * bl, 0.0f);
        accH[r] = pack2(s * bh, 0.0f);
    }

    const u64* wrowL = &Ws2[l * WPITCH];
    const u64* wrowH = &Ws2[(l + 32) * WPITCH];
    #pragma unroll 4
    for (int kp = 0; kp < D / 2; kp++) {
        ulonglong2 x01 = *reinterpret_cast<const ulonglong2*>(&Xst2[kp * XPITCH + r0]);
        ulonglong2 x23 = *reinterpret_cast<const ulonglong2*>(&Xst2[kp * XPITCH + r0 + 2]);
        u64 wl = wrowL[kp];
        u64 wh = wrowH[kp];
        accL[0] = ffma2(x01.x, wl, accL[0]);  accH[0] = ffma2(x01.x, wh, accH[0]);
        accL[1] = ffma2(x01.y, wl, accL[1]);  accH[1] = ffma2(x01.y, wh, accH[1]);
        accL[2] = ffma2(x23.x, wl, accL[2]);  accH[2] = ffma2(x23.x, wh, accH[2]);
        accL[3] = ffma2(x23.y, wl, accL[3]);  accH[3] = ffma2(x23.y, wh, accH[3]);
    }

    #pragma unroll
    for (int r = 0; r < 4; r++) {
        float vL = lo32(accL[r]) + hi32(accL[r]);
        float vH = lo32(accH[r]) + hi32(accH[r]);
        vL = (vL >= 0.0f) ? vL : 0.01f * vL;
        vH = (vH >= 0.0f) ? vH : 0.01f * vH;
        float ss = vL * vL + vH * vH;
        #pragma unroll
        for (int o = 16; o > 0; o >>= 1) ss += __shfl_xor_sync(0xffffffffu, ss, o);
        int row = row0 + r0 + r;
        if (row < N) {
            float inv = 1.0f / fmaxf(sqrtf(ss), 1e-12f);
            out[(size_t)row * D + l]      = vL * inv;
            out[(size_t)row * D + l + 32] = vH * inv;
        }
    }
}

// ---------------------------------------------------------------------------
// Launch
// ---------------------------------------------------------------------------
extern "C" void kernel_launch(void* const* d_in, const int* in_sizes, int n_in,
                              void* d_out, int out_size) {
    const float* poi  = (const float*)d_in[0];
    const int*   eidx = (const int*)d_in[1];
    const float* dist = (const float*)d_in[2];
    const float* W    = (const float*)d_in[3];
    const float* b    = (const float*)d_in[4];
    float* out = (float*)d_out;

    int N = in_sizes[0] / D;
    int E = in_sizes[1] / 2;
    const int* n1 = eidx;
    const int* n2 = eidx + E;
    int nb = (N + SCAN_BS - 1) / SCAN_BS;

    zero_deg_kernel<<<(N + 255) / 256, 256>>>(N);
    deg_kernel<<<(E + 255) / 256, 256>>>(n1, E);
    scan1_kernel<<<nb, SCAN_BS>>>(N);
    scan2_kernel<<<1, 32>>>(nb);
    scan3_kernel<<<nb, SCAN_BS>>>(N);
    scatter_kernel<<<(E + 255) / 256, 256>>>(n1, n2, dist, E);
    {
        long long threads = (long long)N * 16;
        int blocks = (int)((threads + 255) / 256);
        gather_kernel<<<blocks, 256>>>(poi, out, N);
    }
    {
        int blocks = (N + PB_ROWS - 1) / PB_ROWS;
        post_kernel<<<blocks, 256>>>(W, b, out, N);
    }
}

// round 6
// speedup vs baseline: 2.0030x; 1.0468x over previous
#include <cuda_runtime.h>
#include <cuda_bf16.h>

#define D 64
#define NMAX 100000
#define EMAX 1280000
#define SCAN_BS 1024

__device__ int   g_degi[NMAX];     // out-degree (int)
__device__ int   g_rowptr[NMAX];   // CSR row start
__device__ int   g_cur[NMAX];      // scatter cursors
__device__ int   g_bsums[256];     // scan block sums
__device__ float g_sw[NMAX];       // per-node sum of edge weights
__device__ int2  g_epack[EMAX];    // {dst node, weight bits} in CSR order

typedef unsigned long long u64;
__device__ __forceinline__ u64 ffma2(u64 a, u64 b, u64 c) {
    u64 d;
    asm("fma.rn.f32x2 %0, %1, %2, %3;" : "=l"(d) : "l"(a), "l"(b), "l"(c));
    return d;
}
__device__ __forceinline__ u64 pack2(float lo, float hi) {
    u64 d;
    asm("mov.b64 %0, {%1, %2};" : "=l"(d) : "f"(lo), "f"(hi));
    return d;
}
__device__ __forceinline__ float lo32(u64 v) { return __uint_as_float((unsigned)v); }
__device__ __forceinline__ float hi32(u64 v) { return __uint_as_float((unsigned)(v >> 32)); }

// ---------------------------------------------------------------------------
// 1. zero degree counters
// ---------------------------------------------------------------------------
__global__ void zero_deg_kernel(int N) {
    int i = blockIdx.x * blockDim.x + threadIdx.x;
    if (i < N) g_degi[i] = 0;
}

// ---------------------------------------------------------------------------
// 2. degree histogram over source nodes
// ---------------------------------------------------------------------------
__global__ void deg_kernel(const int* __restrict__ n1, int E) {
    int e = blockIdx.x * blockDim.x + threadIdx.x;
    if (e < E) atomicAdd(&g_degi[n1[e]], 1);
}

// ---------------------------------------------------------------------------
// 3-5. exclusive prefix scan of g_degi -> g_rowptr
// ---------------------------------------------------------------------------
__global__ void scan1_kernel(int N) {
    __shared__ int s[SCAN_BS];
    int tid = threadIdx.x;
    int i = blockIdx.x * SCAN_BS + tid;
    int v = (i < N) ? g_degi[i] : 0;
    s[tid] = v;
    __syncthreads();
    #pragma unroll
    for (int off = 1; off < SCAN_BS; off <<= 1) {
        int t = (tid >= off) ? s[tid - off] : 0;
        __syncthreads();
        s[tid] += t;
        __syncthreads();
    }
    if (i < N) g_rowptr[i] = s[tid] - v;   // exclusive within block
    if (tid == SCAN_BS - 1) g_bsums[blockIdx.x] = s[tid];
}

// parallel scan over block sums (nb <= 128), 1 block of 128 threads
__global__ void scan2_kernel(int nb) {
    __shared__ int wsum[4];
    int tid = threadIdx.x;
    int lane = tid & 31;
    int w = tid >> 5;
    int v = (tid < nb) ? g_bsums[tid] : 0;
    int inc = v;
    #pragma unroll
    for (int off = 1; off < 32; off <<= 1) {
        int t = __shfl_up_sync(0xffffffffu, inc, off);
        if (lane >= off) inc += t;
    }
    if (lane == 31) wsum[w] = inc;
    __syncthreads();
    int base = 0;
    #pragma unroll
    for (int k = 0; k < 4; k++) base += (k < w) ? wsum[k] : 0;
    if (tid < nb) g_bsums[tid] = base + inc - v;   // exclusive
}

__global__ void scan3_kernel(int N) {
    int i = blockIdx.x * SCAN_BS + threadIdx.x;
    if (i < N) {
        int r = g_rowptr[i] + g_bsums[blockIdx.x];
        g_rowptr[i] = r;
        g_cur[i] = r;
    }
}

// ---------------------------------------------------------------------------
// 6. scatter edges into CSR order with precomputed weights
// ---------------------------------------------------------------------------
__global__ void scatter_kernel(const int* __restrict__ n1,
                               const int* __restrict__ n2,
                               const float* __restrict__ dist,
                               int E) {
    int e = blockIdx.x * blockDim.x + threadIdx.x;
    if (e >= E) return;
    int a = n1[e];
    int c = n2[e];
    float dv = dist[e];
    float w = rsqrtf(__int2float_rn(g_degi[a]) * __int2float_rn(g_degi[c])) * __expf(-dv * dv);
    int pos = atomicAdd(&g_cur[a], 1);
    g_epack[pos] = make_int2(c, __float_as_int(w));
}

// ---------------------------------------------------------------------------
// 7. per-node gather-accumulate: 16 lanes per node, register accumulation,
//    single write of agg row + sum of weights. No output atomics.
// ---------------------------------------------------------------------------
__global__ __launch_bounds__(256) void gather_kernel(const float* __restrict__ X,
                                                     float* __restrict__ out,
                                                     int N) {
    int gid = blockIdx.x * blockDim.x + threadIdx.x;
    int v = gid >> 4;            // node id
    int sub = gid & 15;          // float4 chunk within the 64-float row
    if (v >= N) return;

    int start = g_rowptr[v];
    int cnt = g_degi[v];
    const float4* X4 = reinterpret_cast<const float4*>(X);

    float4 acc = make_float4(0.f, 0.f, 0.f, 0.f);
    float swl = 0.0f;
    for (int j = 0; j < cnt; j++) {
        int2 p = g_epack[start + j];             // broadcast within 16-lane group
        float w = __int_as_float(p.y);
        swl += w;
        float4 x = X4[(size_t)p.x * 16 + sub];
        acc.x = fmaf(w, x.x, acc.x);
        acc.y = fmaf(w, x.y, acc.y);
        acc.z = fmaf(w, x.z, acc.z);
        acc.w = fmaf(w, x.w, acc.w);
    }
    reinterpret_cast<float4*>(out)[(size_t)v * 16 + sub] = acc;
    if (sub == 0) g_sw[v] = swl;
}

// ---------------------------------------------------------------------------
// 8. Post: y = agg @ W^T + sw*b, leaky_relu, L2 normalize. In-place on out.
// 256 threads, 64 rows/block, 8 rows per warp. f32x2 acc packed over even/odd
// k (final = lo+hi), W in natural row-major u64 pairs.
// ---------------------------------------------------------------------------
#define PB_ROWS 64
#define WPITCH 33   // u64 pitch for Ws2 rows
#define XPITCH 66   // u64 pitch for Xst2 rows (even -> 16B aligned)
__global__ __launch_bounds__(256) void post_kernel(const float* __restrict__ W,
                                                   const float* __restrict__ b,
                                                   float* __restrict__ out, int N) {
    __shared__ u64 Ws2[D * WPITCH];            // 16.9 KB
    __shared__ u64 Xst2[(D / 2) * XPITCH];     // 16.9 KB
    __shared__ float sws[PB_ROWS];

    int tid = threadIdx.x;
    int wid = tid >> 5;
    int l = tid & 31;
    int row0 = blockIdx.x * PB_ROWS;

    const u64* W2 = reinterpret_cast<const u64*>(W);
    #pragma unroll
    for (int i = tid; i < D * (D / 2); i += 256) {
        int j = i >> 5, kp = i & 31;
        Ws2[j * WPITCH + kp] = W2[i];
    }
    const u64* O2 = reinterpret_cast<const u64*>(out);
    #pragma unroll
    for (int i = tid; i < PB_ROWS * (D / 2); i += 256) {
        int r = i >> 5, kp = i & 31;
        int row = row0 + r;
        Xst2[kp * XPITCH + r] = (row < N) ? O2[(size_t)row * (D / 2) + kp] : 0ull;
    }
    if (tid < PB_ROWS) {
        int row = row0 + tid;
        sws[tid] = (row < N) ? g_sw[row] : 0.0f;
    }
    __syncthreads();

    int r0 = wid * 8;
    float bl = b[l], bh = b[l + 32];
    u64 accL[8], accH[8];
    #pragma unroll
    for (int r = 0; r < 8; r++) {
        float s = sws[r0 + r];
        accL[r] = pack2(s * bl, 0.0f);
        accH[r] = pack2(s * bh, 0.0f);
    }

    const u64* wrowL = &Ws2[l * WPITCH];
    const u64* wrowH = &Ws2[(l + 32) * WPITCH];
    #pragma unroll 2
    for (int kp = 0; kp < D / 2; kp++) {
        const u64* xr = &Xst2[kp * XPITCH + r0];
        ulonglong2 x01 = *reinterpret_cast<const ulonglong2*>(xr);
        ulonglong2 x23 = *reinterpret_cast<const ulonglong2*>(xr + 2);
        ulonglong2 x45 = *reinterpret_cast<const ulonglong2*>(xr + 4);
        ulonglong2 x67 = *reinterpret_cast<const ulonglong2*>(xr + 6);
        u64 wl = wrowL[kp];
        u64 wh = wrowH[kp];
        accL[0] = ffma2(x01.x, wl, accL[0]);  accH[0] = ffma2(x01.x, wh, accH[0]);
        accL[1] = ffma2(x01.y, wl, accL[1]);  accH[1] = ffma2(x01.y, wh, accH[1]);
        accL[2] = ffma2(x23.x, wl, accL[2]);  accH[2] = ffma2(x23.x, wh, accH[2]);
        accL[3] = ffma2(x23.y, wl, accL[3]);  accH[3] = ffma2(x23.y, wh, accH[3]);
        accL[4] = ffma2(x45.x, wl, accL[4]);  accH[4] = ffma2(x45.x, wh, accH[4]);
        accL[5] = ffma2(x45.y, wl, accL[5]);  accH[5] = ffma2(x45.y, wh, accH[5]);
        accL[6] = ffma2(x67.x, wl, accL[6]);  accH[6] = ffma2(x67.x, wh, accH[6]);
        accL[7] = ffma2(x67.y, wl, accL[7]);  accH[7] = ffma2(x67.y, wh, accH[7]);
    }

    #pragma unroll
    for (int r = 0; r < 8; r++) {
        float vL = lo32(accL[r]) + hi32(accL[r]);
        float vH = lo32(accH[r]) + hi32(accH[r]);
        vL = (vL >= 0.0f) ? vL : 0.01f * vL;
        vH = (vH >= 0.0f) ? vH : 0.01f * vH;
        float ss = vL * vL + vH * vH;
        #pragma unroll
        for (int o = 16; o > 0; o >>= 1) ss += __shfl_xor_sync(0xffffffffu, ss, o);
        int row = row0 + r0 + r;
        if (row < N) {
            float inv = 1.0f / fmaxf(sqrtf(ss), 1e-12f);
            out[(size_t)row * D + l]      = vL * inv;
            out[(size_t)row * D + l + 32] = vH * inv;
        }
    }
}

// ---------------------------------------------------------------------------
// Launch
// ---------------------------------------------------------------------------
extern "C" void kernel_launch(void* const* d_in, const int* in_sizes, int n_in,
                              void* d_out, int out_size) {
    const float* poi  = (const float*)d_in[0];
    const int*   eidx = (const int*)d_in[1];
    const float* dist = (const float*)d_in[2];
    const float* W    = (const float*)d_in[3];
    const float* b    = (const float*)d_in[4];
    float* out = (float*)d_out;

    int N = in_sizes[0] / D;
    int E = in_sizes[1] / 2;
    const int* n1 = eidx;
    const int* n2 = eidx + E;
    int nb = (N + SCAN_BS - 1) / SCAN_BS;

    zero_deg_kernel<<<(N + 255) / 256, 256>>>(N);
    deg_kernel<<<(E + 255) / 256, 256>>>(n1, E);
    scan1_kernel<<<nb, SCAN_BS>>>(N);
    scan2_kernel<<<1, 128>>>(nb);
    scan3_kernel<<<nb, SCAN_BS>>>(N);
    scatter_kernel<<<(E + 255) / 256, 256>>>(n1, n2, dist, E);
    {
        long long threads = (long long)N * 16;
        int blocks = (int)((threads + 255) / 256);
        gather_kernel<<<blocks, 256>>>(poi, out, N);
    }
    {
        int blocks = (N + PB_ROWS - 1) / PB_ROWS;
        post_kernel<<<blocks, 256>>>(W, b, out, N);
    }
}